// round 1
// baseline (speedup 1.0000x reference)
#include <cuda_runtime.h>
#include <math_constants.h>

// Problem constants (from reference)
#define BB 4096
#define PP 128
#define GG 128

// SCALE = SPACE_SIZE / (VOXELS_PER_AXIS - 1), BIAS = SPACE_CENTER - SPACE_SIZE/2
#define SCX (8000.0f / 79.0f)
#define SCY (8000.0f / 79.0f)
#define SCZ (2000.0f / 19.0f)
#define BX (-4000.0f)
#define BY (-4000.0f)
#define BZ (0.0f)

#define DIST_THRESH_SQ (500.0f * 500.0f)
#define BBOX_THRESH 0.1f

__global__ __launch_bounds__(PP, 8)
void proposal_layer_kernel(const int*   __restrict__ topk_index,      // [B,P,3] int32
                           const float* __restrict__ topk_confs,      // [B,P]
                           const float* __restrict__ match_bbox_preds,// [B,P,2]
                           const float* __restrict__ roots_3d,        // [B,G,3]
                           const float* __restrict__ gt_bbox,         // [B,G,2]
                           const int*   __restrict__ num_person,      // [B]
                           float*       __restrict__ out)             // [B,P,7]
{
    const int b = blockIdx.x;
    const int p = threadIdx.x;  // 0..127

    __shared__ float4 s_roots[GG];     // xyz + pad
    __shared__ float2 s_bbox[GG];
    __shared__ float  s_out[PP * 7];

    // cooperative stage: one g per thread (P == G == 128)
    {
        const float* r = roots_3d + ((size_t)b * GG + p) * 3;
        float4 v;
        v.x = r[0]; v.y = r[1]; v.z = r[2]; v.w = 0.0f;
        s_roots[p] = v;
        const float* gb = gt_bbox + ((size_t)b * GG + p) * 2;
        s_bbox[p] = make_float2(gb[0], gb[1]);
    }
    const int n = num_person[b];  // uniform across block, >= 1
    __syncthreads();

    // per-proposal inputs
    const int* ti = topk_index + ((size_t)b * PP + p) * 3;
    const float cx = (float)ti[0] * SCX + BX;
    const float cy = (float)ti[1] * SCY + BY;
    const float cz = (float)ti[2] * SCZ + BZ;

    const float conf = topk_confs[(size_t)b * PP + p];
    const float* mp = match_bbox_preds + ((size_t)b * PP + p) * 2;
    const float pb0 = mp[0];
    const float pb1 = mp[1];

    // argmin over valid gt of squared distance (monotone in distance)
    float best = CUDART_INF_F;
    int   bidx = 0;
    #pragma unroll 4
    for (int g = 0; g < n; ++g) {
        float4 r = s_roots[g];            // LDS.128 broadcast
        float dx = cx - r.x;
        float dy = cy - r.y;
        float dz = cz - r.z;
        float d2 = dx * dx + dy * dy + dz * dz;
        bool lt = d2 < best;              // strict < keeps first min (matches argmin)
        best = lt ? d2 : best;
        bidx = lt ? g : bidx;
    }

    const bool matched = !(best > DIST_THRESH_SQ);  // dist <= 500  <=>  d2 <= 500^2
    const float p2g = matched ? (float)bidx : -1.0f;

    // conditional bbox overwrite
    float2 mb = s_bbox[bidx];
    bool ow = matched && ((pb0 < mb.x - BBOX_THRESH) || (pb1 < mb.y - BBOX_THRESH));
    const float o5 = ow ? mb.x : pb0;
    const float o6 = ow ? mb.y : pb1;

    // stage [P,7] tile in shared (stride 7 => conflict-free, gcd(7,32)=1)
    float* so = s_out + p * 7;
    so[0] = cx; so[1] = cy; so[2] = cz;
    so[3] = p2g; so[4] = conf;
    so[5] = o5;  so[6] = o6;
    __syncthreads();

    // coalesced store of 896 floats
    float* ob = out + (size_t)b * (PP * 7);
    #pragma unroll
    for (int i = p; i < PP * 7; i += PP)
        ob[i] = s_out[i];
}

extern "C" void kernel_launch(void* const* d_in, const int* in_sizes, int n_in,
                              void* d_out, int out_size)
{
    const int*   topk_index       = (const int*)  d_in[0];
    const float* topk_confs       = (const float*)d_in[1];
    const float* match_bbox_preds = (const float*)d_in[2];
    const float* roots_3d         = (const float*)d_in[3];
    const float* gt_bbox          = (const float*)d_in[4];
    const int*   num_person       = (const int*)  d_in[5];
    float* out = (float*)d_out;

    proposal_layer_kernel<<<BB, PP>>>(topk_index, topk_confs, match_bbox_preds,
                                      roots_3d, gt_bbox, num_person, out);
}

// round 2
// speedup vs baseline: 1.1473x; 1.1473x over previous
#include <cuda_runtime.h>
#include <math_constants.h>

#define BB 4096
#define PP 128
#define GG 128

#define SCX (8000.0f / 79.0f)
#define SCY (8000.0f / 79.0f)
#define SCZ (2000.0f / 19.0f)
#define BX (-4000.0f)
#define BY (-4000.0f)
#define BZ (0.0f)

#define DIST_THRESH_SQ (500.0f * 500.0f)
#define BBOX_THRESH 0.1f

// ---- packed f32x2 helpers (sm_103a) ----
__device__ __forceinline__ unsigned long long pack2(float lo, float hi) {
    unsigned long long r;
    asm("mov.b64 %0, {%1, %2};" : "=l"(r) : "f"(lo), "f"(hi));
    return r;
}
__device__ __forceinline__ void unpack2(unsigned long long v, float& lo, float& hi) {
    asm("mov.b64 {%0, %1}, %2;" : "=f"(lo), "=f"(hi) : "l"(v));
}
__device__ __forceinline__ unsigned long long add2(unsigned long long a, unsigned long long b) {
    unsigned long long r;
    asm("add.rn.f32x2 %0, %1, %2;" : "=l"(r) : "l"(a), "l"(b));
    return r;
}
__device__ __forceinline__ unsigned long long mul2(unsigned long long a, unsigned long long b) {
    unsigned long long r;
    asm("mul.rn.f32x2 %0, %1, %2;" : "=l"(r) : "l"(a), "l"(b));
    return r;
}
__device__ __forceinline__ unsigned long long fma2(unsigned long long a, unsigned long long b,
                                                   unsigned long long c) {
    unsigned long long r;
    asm("fma.rn.f32x2 %0, %1, %2, %3;" : "=l"(r) : "l"(a), "l"(b), "l"(c));
    return r;
}

__global__ __launch_bounds__(PP, 12)
void proposal_layer_kernel(const int*   __restrict__ topk_index,      // [B,P,3]
                           const float* __restrict__ topk_confs,      // [B,P]
                           const float* __restrict__ match_bbox_preds,// [B,P,2]
                           const float* __restrict__ roots_3d,        // [B,G,3]
                           const float* __restrict__ gt_bbox,         // [B,G,2]
                           const int*   __restrict__ num_person,      // [B]
                           float*       __restrict__ out)             // [B,P,7]
{
    const int b = blockIdx.x;
    const int p = threadIdx.x;  // 0..127

    // negated roots, SoA, 16B aligned so ulonglong2 (LDS.128) covers 4 g's
    __shared__ __align__(16) float s_nx[GG];
    __shared__ __align__(16) float s_ny[GG];
    __shared__ __align__(16) float s_nz[GG];
    __shared__ float2 s_bbox[GG];
    __shared__ float  s_out[PP * 7];

    {
        const float* r = roots_3d + ((size_t)b * GG + p) * 3;
        s_nx[p] = -r[0];
        s_ny[p] = -r[1];
        s_nz[p] = -r[2];
        const float* gb = gt_bbox + ((size_t)b * GG + p) * 2;
        s_bbox[p] = make_float2(gb[0], gb[1]);
    }
    const int n = num_person[b];  // uniform per block, 1..128
    __syncthreads();

    // per-proposal inputs
    const int* ti = topk_index + ((size_t)b * PP + p) * 3;
    const float cx = (float)ti[0] * SCX + BX;
    const float cy = (float)ti[1] * SCY + BY;
    const float cz = (float)ti[2] * SCZ + BZ;

    const float conf = topk_confs[(size_t)b * PP + p];
    const float* mp = match_bbox_preds + ((size_t)b * PP + p) * 2;
    const float pb0 = mp[0];
    const float pb1 = mp[1];

    const unsigned long long cxx = pack2(cx, cx);
    const unsigned long long cyy = pack2(cy, cy);
    const unsigned long long czz = pack2(cz, cz);

    // 4 independent min chains (residue mod 4); chains track block index q
    float best0 = CUDART_INF_F, best1 = CUDART_INF_F,
          best2 = CUDART_INF_F, best3 = CUDART_INF_F;
    int q0 = 0, q1 = 0, q2 = 0, q3 = 0;

    const ulonglong2* px = (const ulonglong2*)s_nx;
    const ulonglong2* py = (const ulonglong2*)s_ny;
    const ulonglong2* pz = (const ulonglong2*)s_nz;

    const int nb = n >> 2;
    for (int q = 0; q < nb; ++q) {
        ulonglong2 X = px[q];  // LDS.128: nx[4q..4q+3] as two f32x2 pairs
        ulonglong2 Y = py[q];
        ulonglong2 Z = pz[q];

        unsigned long long dxA = add2(cxx, X.x), dxB = add2(cxx, X.y);
        unsigned long long dyA = add2(cyy, Y.x), dyB = add2(cyy, Y.y);
        unsigned long long dzA = add2(czz, Z.x), dzB = add2(czz, Z.y);

        unsigned long long sA = mul2(dxA, dxA);
        unsigned long long sB = mul2(dxB, dxB);
        sA = fma2(dyA, dyA, sA);
        sB = fma2(dyB, dyB, sB);
        sA = fma2(dzA, dzA, sA);
        sB = fma2(dzB, dzB, sB);

        float s0, s1, s2, s3;
        unpack2(sA, s0, s1);
        unpack2(sB, s2, s3);

        if (s0 < best0) { best0 = s0; q0 = q; }
        if (s1 < best1) { best1 = s1; q1 = q; }
        if (s2 < best2) { best2 = s2; q2 = q; }
        if (s3 < best3) { best3 = s3; q3 = q; }
    }

    // merge chains (strict < ordering; residue order matches intra-block order)
    float bd = best0; int bi = (q0 << 2);
    if (best1 < bd) { bd = best1; bi = (q1 << 2) + 1; }
    if (best2 < bd) { bd = best2; bi = (q2 << 2) + 2; }
    if (best3 < bd) { bd = best3; bi = (q3 << 2) + 3; }

    // scalar tail (indices >= nb*4 > any chain index; strict < keeps earlier)
    for (int g = (nb << 2); g < n; ++g) {
        float dx = cx + s_nx[g];
        float dy = cy + s_ny[g];
        float dz = cz + s_nz[g];
        float d2 = __fmaf_rn(dz, dz, __fmaf_rn(dy, dy, dx * dx));
        if (d2 < bd) { bd = d2; bi = g; }
    }

    const bool matched = !(bd > DIST_THRESH_SQ);
    const float p2g = matched ? (float)bi : -1.0f;

    float2 mb = s_bbox[bi];
    bool ow = matched && ((pb0 < mb.x - BBOX_THRESH) || (pb1 < mb.y - BBOX_THRESH));
    const float o5 = ow ? mb.x : pb0;
    const float o6 = ow ? mb.y : pb1;

    // stage [P,7] tile in shared (stride 7 -> conflict-free)
    float* so = s_out + p * 7;
    so[0] = cx; so[1] = cy; so[2] = cz;
    so[3] = p2g; so[4] = conf;
    so[5] = o5;  so[6] = o6;
    __syncthreads();

    float* ob = out + (size_t)b * (PP * 7);
    #pragma unroll
    for (int i = p; i < PP * 7; i += PP)
        ob[i] = s_out[i];
}

extern "C" void kernel_launch(void* const* d_in, const int* in_sizes, int n_in,
                              void* d_out, int out_size)
{
    const int*   topk_index       = (const int*)  d_in[0];
    const float* topk_confs       = (const float*)d_in[1];
    const float* match_bbox_preds = (const float*)d_in[2];
    const float* roots_3d         = (const float*)d_in[3];
    const float* gt_bbox          = (const float*)d_in[4];
    const int*   num_person       = (const int*)  d_in[5];
    float* out = (float*)d_out;

    proposal_layer_kernel<<<BB, PP>>>(topk_index, topk_confs, match_bbox_preds,
                                      roots_3d, gt_bbox, num_person, out);
}